// round 1
// baseline (speedup 1.0000x reference)
#include <cuda_runtime.h>

// SO3Linear: out[b,m,o] = sum_i in[b,m,i] * (w[l(m),o,i] - bound)  (+ bias[o] at m==0)
// B=16384, NUM_M=25, IN=OUT=128. 25 independent GEMMs grouped by blockIdx.y=m.
//
// Round 1: fp32 SIMT SGEMM baseline. 128x128x128 tile per CTA, 256 threads,
// 8x8 register tile per thread, k-vectorized by float4. Both A and W stored
// k-major in smem (natural layout, no transpose), PAD=132 floats per row.

#define BATCH      16384
#define NUM_M      25
#define IN_F       128
#define OUT_F      128
#define TILE_M     128          // batch rows per CTA
#define PAD        132          // smem row stride in floats (16B-aligned rows)
#define NTHREADS   256

#define SMEM_BYTES (2 * 128 * PAD * 4)

__global__ __launch_bounds__(NTHREADS, 1)
void so3linear_kernel(const float* __restrict__ in,
                      const float* __restrict__ w,
                      const float* __restrict__ bias,
                      float* __restrict__ out) {
    extern __shared__ float smem[];
    float* As = smem;                 // [128][PAD]  rows = batch rows, cols = k
    float* Ws = smem + 128 * PAD;     // [128][PAD]  rows = out cols,  cols = k

    const int m   = blockIdx.y;
    const int l   = (m >= 16) ? 4 : (m >= 9) ? 3 : (m >= 4) ? 2 : (m >= 1) ? 1 : 0;
    const int b0  = blockIdx.x * TILE_M;
    const int tid = threadIdx.x;

    const float bound = 0.088388347648318447f;  // 1/sqrt(128)

    // ---- Load phase: A tile (128 rows x 128 k) and W_l (128 out x 128 k) ----
    // 4096 float4 each; 256 threads x 16 iters. Each warp reads one full
    // 512B row per instruction (fully coalesced); smem stores conflict-free.
    const float* wl = w + (size_t)l * OUT_F * IN_F;
#pragma unroll
    for (int it = 0; it < 16; ++it) {
        int li  = it * NTHREADS + tid;
        int row = li >> 5;        // 0..127
        int c4  = li & 31;        // float4 column

        float4 av = *reinterpret_cast<const float4*>(
            in + ((size_t)(b0 + row) * NUM_M + m) * IN_F + c4 * 4);
        *reinterpret_cast<float4*>(As + row * PAD + c4 * 4) = av;

        float4 wv = *reinterpret_cast<const float4*>(
            wl + (size_t)row * IN_F + c4 * 4);
        wv.x -= bound; wv.y -= bound; wv.z -= bound; wv.w -= bound;
        *reinterpret_cast<float4*>(Ws + row * PAD + c4 * 4) = wv;
    }
    __syncthreads();

    // ---- Compute: each thread owns 8 rows x 8 cols ----
    // rows = {4*tx..4*tx+3, 64+4*tx..}, cols = {4*ty..4*ty+3, 64+4*ty..}
    const int tx = tid & 15;
    const int ty = tid >> 4;
    const int r0 = tx * 4;
    const int c0 = ty * 4;

    float acc[8][8];
#pragma unroll
    for (int i = 0; i < 8; ++i)
#pragma unroll
        for (int j = 0; j < 8; ++j) acc[i][j] = 0.0f;

#pragma unroll 4
    for (int kk = 0; kk < 128; kk += 4) {
        float4 a[8], wv[8];
#pragma unroll
        for (int i = 0; i < 4; ++i) {
            a[i]      = *reinterpret_cast<const float4*>(As + (r0 + i) * PAD + kk);
            a[4 + i]  = *reinterpret_cast<const float4*>(As + (64 + r0 + i) * PAD + kk);
            wv[i]     = *reinterpret_cast<const float4*>(Ws + (c0 + i) * PAD + kk);
            wv[4 + i] = *reinterpret_cast<const float4*>(Ws + (64 + c0 + i) * PAD + kk);
        }
#pragma unroll
        for (int i = 0; i < 8; ++i) {
#pragma unroll
            for (int j = 0; j < 8; ++j) {
                acc[i][j] += a[i].x * wv[j].x;
                acc[i][j] += a[i].y * wv[j].y;
                acc[i][j] += a[i].z * wv[j].z;
                acc[i][j] += a[i].w * wv[j].w;
            }
        }
    }

    // ---- Epilogue: bias only for m == 0, float4 stores ----
    float blo[4] = {0.f, 0.f, 0.f, 0.f};
    float bhi[4] = {0.f, 0.f, 0.f, 0.f};
    if (m == 0) {
#pragma unroll
        for (int j = 0; j < 4; ++j) {
            blo[j] = bias[c0 + j];
            bhi[j] = bias[64 + c0 + j];
        }
    }

#pragma unroll
    for (int ri = 0; ri < 8; ++ri) {
        int r = (ri < 4) ? (r0 + ri) : (64 + r0 + (ri - 4));
        size_t base = ((size_t)(b0 + r) * NUM_M + m) * OUT_F;
        float4 v0, v1;
        v0.x = acc[ri][0] + blo[0];
        v0.y = acc[ri][1] + blo[1];
        v0.z = acc[ri][2] + blo[2];
        v0.w = acc[ri][3] + blo[3];
        v1.x = acc[ri][4] + bhi[0];
        v1.y = acc[ri][5] + bhi[1];
        v1.z = acc[ri][6] + bhi[2];
        v1.w = acc[ri][7] + bhi[3];
        *reinterpret_cast<float4*>(out + base + c0)      = v0;
        *reinterpret_cast<float4*>(out + base + 64 + c0) = v1;
    }
}

extern "C" void kernel_launch(void* const* d_in, const int* in_sizes, int n_in,
                              void* d_out, int out_size) {
    const float* in   = (const float*)d_in[0];  // [16384, 25, 128]
    const float* w    = (const float*)d_in[1];  // [5, 128, 128]
    const float* bias = (const float*)d_in[2];  // [128]
    float* out        = (float*)d_out;          // [16384, 25, 128]

    cudaFuncSetAttribute(so3linear_kernel,
                         cudaFuncAttributeMaxDynamicSharedMemorySize, SMEM_BYTES);

    dim3 grid(BATCH / TILE_M, NUM_M);  // (128, 25) = 3200 CTAs
    so3linear_kernel<<<grid, NTHREADS, SMEM_BYTES>>>(in, w, bias, out);
}

// round 3
// speedup vs baseline: 3.3659x; 3.3659x over previous
#include <cuda_runtime.h>
#include <cuda_bf16.h>
#include <cstdint>

// SO3Linear via mma.sync bf16 (HMMA) with 3-MMA compensated hi/lo split.
// out[b,m,o] = sum_i in[b,m,i]*(w[l(m),o,i]-bound), + bias[o] at m==0.
// Per CTA: 64 batch rows x one m. D[64,128] = A[64,128] . W^T (k-major both).
// x = hi(bf16) + lo(bf16); D = Ah*Wh + Al*Wh + Ah*Wl in fp32 accumulators.
// NOTE: tcgen05/TMA unavailable (ptxas target is plain sm_103, no 'a' features).

#define BATCH    16384
#define NUM_M    25
#define IN_F     128
#define OUT_F    128
#define TILE_B   64
#define NTHREADS 256

// SW128 layout: each tile stored as 2 k-chunks (k 0..63 | 64..127) of 128B rows.
// A chunk: 64 rows *128B = 8192B.  W chunk: 128 rows *128B = 16384B.
#define AH_OFF   0
#define AL_OFF   16384
#define WH_OFF   32768
#define WL_OFF   65536
#define SMEM_BYTES 98304

#define SWZ(b) ((b) ^ (((b) >> 3) & 0x70))

__device__ __forceinline__ uint32_t smem_u32(const void* p) {
    uint32_t a;
    asm("{ .reg .u64 t; cvta.to.shared.u64 t, %1; cvt.u32.u64 %0, t; }" : "=r"(a) : "l"(p));
    return a;
}

#define LDSM4(r, addr) \
    asm volatile("ldmatrix.sync.aligned.m8n8.x4.shared.b16 {%0,%1,%2,%3}, [%4];" \
        : "=r"((r)[0]), "=r"((r)[1]), "=r"((r)[2]), "=r"((r)[3]) : "r"(addr))

#define MMA_BF16(c, a, b0_, b1_) \
    asm volatile("mma.sync.aligned.m16n8k16.row.col.f32.bf16.bf16.f32 " \
        "{%0,%1,%2,%3},{%4,%5,%6,%7},{%8,%9},{%0,%1,%2,%3};" \
        : "+f"((c)[0]), "+f"((c)[1]), "+f"((c)[2]), "+f"((c)[3]) \
        : "r"((a)[0]), "r"((a)[1]), "r"((a)[2]), "r"((a)[3]), "r"(b0_), "r"(b1_))

__device__ __forceinline__ uint32_t pack_bf16(float x, float y) {
    __nv_bfloat162 p(__float2bfloat16(x), __float2bfloat16(y));
    return *reinterpret_cast<uint32_t*>(&p);
}

__global__ __launch_bounds__(NTHREADS, 2)
void so3linear_hmma_kernel(const float* __restrict__ in,
                           const float* __restrict__ w,
                           const float* __restrict__ bias,
                           float* __restrict__ out) {
    extern __shared__ char smem[];
    const uint32_t sb = smem_u32(smem);

    const int tid  = threadIdx.x;
    const int wid  = tid >> 5;
    const int lane = tid & 31;
    const int m    = blockIdx.y;
    const int l    = (m >= 16) ? 4 : (m >= 9) ? 3 : (m >= 4) ? 2 : (m >= 1) ? 1 : 0;
    const int b0   = blockIdx.x * TILE_B;

    const float bound = 0.088388347648318447f;  // 1/sqrt(128)

    const float* aBase = in + ((size_t)b0 * NUM_M + m) * IN_F;
    const float* wBase = w + (size_t)l * OUT_F * IN_F;

    // ---- Convert A tile (64 x 128) -> bf16 hi/lo, SW128 swizzled ----
#pragma unroll
    for (int it = 0; it < 8; ++it) {
        int li = it * NTHREADS + tid;
        int r  = li >> 5;                 // 0..63
        int q  = li & 31;                 // float4 col; k0 = 4q
        uint32_t soff = (uint32_t)(q >> 4) * 8192u + SWZ((uint32_t)(r * 128 + (q & 15) * 8));
        float4 v = *reinterpret_cast<const float4*>(aBase + (size_t)r * (NUM_M * IN_F) + q * 4);
        float hx = __bfloat162float(__float2bfloat16(v.x));
        float hy = __bfloat162float(__float2bfloat16(v.y));
        float hz = __bfloat162float(__float2bfloat16(v.z));
        float hw = __bfloat162float(__float2bfloat16(v.w));
        *reinterpret_cast<uint2*>(smem + AH_OFF + soff) =
            make_uint2(pack_bf16(v.x, v.y), pack_bf16(v.z, v.w));
        *reinterpret_cast<uint2*>(smem + AL_OFF + soff) =
            make_uint2(pack_bf16(v.x - hx, v.y - hy), pack_bf16(v.z - hz, v.w - hw));
    }

    // ---- Convert W_l (128 x 128, centered) -> bf16 hi/lo, SW128 swizzled ----
#pragma unroll
    for (int it = 0; it < 16; ++it) {
        int li = it * NTHREADS + tid;
        int r  = li >> 5;                 // 0..127 (out dim)
        int q  = li & 31;
        uint32_t soff = (uint32_t)(q >> 4) * 16384u + SWZ((uint32_t)(r * 128 + (q & 15) * 8));
        float4 v = *reinterpret_cast<const float4*>(wBase + (size_t)r * IN_F + q * 4);
        v.x -= bound; v.y -= bound; v.z -= bound; v.w -= bound;
        float hx = __bfloat162float(__float2bfloat16(v.x));
        float hy = __bfloat162float(__float2bfloat16(v.y));
        float hz = __bfloat162float(__float2bfloat16(v.z));
        float hw = __bfloat162float(__float2bfloat16(v.w));
        *reinterpret_cast<uint2*>(smem + WH_OFF + soff) =
            make_uint2(pack_bf16(v.x, v.y), pack_bf16(v.z, v.w));
        *reinterpret_cast<uint2*>(smem + WL_OFF + soff) =
            make_uint2(pack_bf16(v.x - hx, v.y - hy), pack_bf16(v.z - hz, v.w - hw));
    }
    __syncthreads();

    // ---- Warp tiles: wid&1 -> m block (32 rows), wid>>1 -> n block (32 cols) ----
    const int m0 = (wid & 1) * 32;
    const int n0 = (wid >> 1) * 32;
    const int row_in = (lane & 7) + ((lane >> 3) & 1) * 8;  // ldmatrix lane row
    const int kadd   = (lane >> 4) * 8;                     // ldmatrix lane k offset

    float acc[2][4][4];
#pragma unroll
    for (int a = 0; a < 2; ++a)
#pragma unroll
        for (int b = 0; b < 4; ++b)
#pragma unroll
            for (int c = 0; c < 4; ++c) acc[a][b][c] = 0.0f;

#pragma unroll
    for (int ks = 0; ks < 8; ++ks) {
        const int kc    = ks * 16 + kadd;
        const int chunk = kc >> 6;
        const int kwi   = (kc & 63) * 2;      // byte offset within 128B row

        uint32_t ah[2][4], al[2][4], wh[2][4], wl[2][4];
#pragma unroll
        for (int mt = 0; mt < 2; ++mt) {
            uint32_t addr = sb + AH_OFF + (uint32_t)chunk * 8192u +
                            SWZ((uint32_t)((m0 + mt * 16 + row_in) * 128 + kwi));
            LDSM4(ah[mt], addr);
            LDSM4(al[mt], addr + (AL_OFF - AH_OFF));
        }
#pragma unroll
        for (int g = 0; g < 2; ++g) {
            uint32_t addr = sb + WH_OFF + (uint32_t)chunk * 16384u +
                            SWZ((uint32_t)((n0 + g * 16 + row_in) * 128 + kwi));
            LDSM4(wh[g], addr);
            LDSM4(wl[g], addr + (WL_OFF - WH_OFF));
        }
#pragma unroll
        for (int mt = 0; mt < 2; ++mt) {
#pragma unroll
            for (int nt = 0; nt < 4; ++nt) {
                const int g = nt >> 1, o = nt & 1;
                MMA_BF16(acc[mt][nt], ah[mt], wh[g][o], wh[g][2 + o]);
                MMA_BF16(acc[mt][nt], al[mt], wh[g][o], wh[g][2 + o]);
                MMA_BF16(acc[mt][nt], ah[mt], wl[g][o], wl[g][2 + o]);
            }
        }
    }

    // ---- Epilogue: direct STG.64, bias on m==0 ----
    float2 bv[4];
#pragma unroll
    for (int nt = 0; nt < 4; ++nt) {
        int col = n0 + nt * 8 + (lane & 3) * 2;
        if (m == 0) {
            bv[nt].x = bias[col];
            bv[nt].y = bias[col + 1];
        } else {
            bv[nt].x = 0.0f; bv[nt].y = 0.0f;
        }
    }
#pragma unroll
    for (int mt = 0; mt < 2; ++mt) {
#pragma unroll
        for (int nt = 0; nt < 4; ++nt) {
#pragma unroll
            for (int h = 0; h < 2; ++h) {
                int row = b0 + m0 + mt * 16 + (lane >> 2) + h * 8;
                int col = n0 + nt * 8 + (lane & 3) * 2;
                float2 v;
                v.x = acc[mt][nt][2 * h]     + bv[nt].x;
                v.y = acc[mt][nt][2 * h + 1] + bv[nt].y;
                *reinterpret_cast<float2*>(
                    out + ((size_t)row * NUM_M + m) * OUT_F + col) = v;
            }
        }
    }
}

extern "C" void kernel_launch(void* const* d_in, const int* in_sizes, int n_in,
                              void* d_out, int out_size) {
    const float* in   = (const float*)d_in[0];  // [16384, 25, 128]
    const float* w    = (const float*)d_in[1];  // [5, 128, 128]
    const float* bias = (const float*)d_in[2];  // [128]
    float* out        = (float*)d_out;          // [16384, 25, 128]

    cudaFuncSetAttribute(so3linear_hmma_kernel,
                         cudaFuncAttributeMaxDynamicSharedMemorySize, SMEM_BYTES);

    dim3 grid(BATCH / TILE_B, NUM_M);  // (256, 25) = 6400 CTAs
    so3linear_hmma_kernel<<<grid, NTHREADS, SMEM_BYTES>>>(in, w, bias, out);
}

// round 5
// speedup vs baseline: 3.4661x; 1.0298x over previous
#include <cuda_runtime.h>
#include <cuda_bf16.h>
#include <cstdint>

// SO3Linear via mma.sync bf16 (HMMA), 3-MMA compensated hi/lo split.
// R4: W precomputed once (prep kernel) into SW128 smem-image layout in a
// __device__ global; main kernel cp.asyncs it in as a flat 64KB copy and
// amortizes it over 4 batch tiles per CTA.

#define BATCH    16384
#define NUM_M    25
#define IN_F     128
#define OUT_F    128
#define TILE_B   64
#define NTILE    4
#define NTHREADS 256

// W prep layout per l (64KB): [hi c0 16K][hi c1 16K][lo c0 16K][lo c1 16K]
// chunk c = k range [64c, 64c+63], 128B swizzled rows.
#define W_L_BYTES   65536
#define W_CH_STRIDE 16384
#define WL_REL      32768
// smem: W image at 0 (64KB), then A hi (16KB: c0,c1 of 8KB), A lo (16KB).
#define AH_OFF      65536
#define AL_OFF      81920
#define A_CH_STRIDE 8192
#define SMEM_BYTES  98304

#define SWZ(b) ((b) ^ (((b) >> 3) & 0x70))

__device__ __align__(128) uint8_t g_wprep[5 * W_L_BYTES];

__device__ __forceinline__ uint32_t smem_u32(const void* p) {
    uint32_t a;
    asm("{ .reg .u64 t; cvta.to.shared.u64 t, %1; cvt.u32.u64 %0, t; }" : "=r"(a) : "l"(p));
    return a;
}

#define LDSM4(r, addr) \
    asm volatile("ldmatrix.sync.aligned.m8n8.x4.shared.b16 {%0,%1,%2,%3}, [%4];" \
        : "=r"((r)[0]), "=r"((r)[1]), "=r"((r)[2]), "=r"((r)[3]) : "r"(addr))

#define MMA_BF16(c, a, b0_, b1_) \
    asm volatile("mma.sync.aligned.m16n8k16.row.col.f32.bf16.bf16.f32 " \
        "{%0,%1,%2,%3},{%4,%5,%6,%7},{%8,%9},{%0,%1,%2,%3};" \
        : "+f"((c)[0]), "+f"((c)[1]), "+f"((c)[2]), "+f"((c)[3]) \
        : "r"((a)[0]), "r"((a)[1]), "r"((a)[2]), "r"((a)[3]), "r"(b0_), "r"(b1_))

__device__ __forceinline__ uint32_t pack_bf16(float x, float y) {
    __nv_bfloat162 p(__float2bfloat16(x), __float2bfloat16(y));
    return *reinterpret_cast<uint32_t*>(&p);
}

// ---- Prep: W[l] -> centered bf16 hi/lo, SW128 smem-image layout in global ----
__global__ void so3_prep_w(const float* __restrict__ w) {
    const int l   = blockIdx.x;
    const int tid = threadIdx.x;
    const float bound = 0.088388347648318447f;  // 1/sqrt(128)
    uint8_t* dst = g_wprep + (size_t)l * W_L_BYTES;
    const float* src = w + (size_t)l * OUT_F * IN_F;
#pragma unroll
    for (int it = 0; it < 16; ++it) {
        int li = it * NTHREADS + tid;
        int r  = li >> 5;                 // out row 0..127
        int q  = li & 31;                 // float4 col, k0 = 4q
        uint32_t soff = (uint32_t)(q >> 4) * W_CH_STRIDE +
                        SWZ((uint32_t)(r * 128 + (q & 15) * 8));
        float4 v = *reinterpret_cast<const float4*>(src + (size_t)r * IN_F + q * 4);
        v.x -= bound; v.y -= bound; v.z -= bound; v.w -= bound;
        float hx = __bfloat162float(__float2bfloat16(v.x));
        float hy = __bfloat162float(__float2bfloat16(v.y));
        float hz = __bfloat162float(__float2bfloat16(v.z));
        float hw = __bfloat162float(__float2bfloat16(v.w));
        *reinterpret_cast<uint2*>(dst + soff) =
            make_uint2(pack_bf16(v.x, v.y), pack_bf16(v.z, v.w));
        *reinterpret_cast<uint2*>(dst + WL_REL + soff) =
            make_uint2(pack_bf16(v.x - hx, v.y - hy), pack_bf16(v.z - hz, v.w - hw));
    }
}

// ---- Main kernel ----
__global__ __launch_bounds__(NTHREADS, 2)
void so3linear_hmma_kernel(const float* __restrict__ in,
                           const float* __restrict__ bias,
                           float* __restrict__ out) {
    extern __shared__ char smem[];
    const uint32_t sb = smem_u32(smem);

    const int tid  = threadIdx.x;
    const int wid  = tid >> 5;
    const int lane = tid & 31;
    const int m    = blockIdx.y;
    const int l    = (m >= 16) ? 4 : (m >= 9) ? 3 : (m >= 4) ? 2 : (m >= 1) ? 1 : 0;

    // ---- W: flat 64KB cp.async from prepped image ----
    {
        const uint8_t* wsrc = g_wprep + (size_t)l * W_L_BYTES;
#pragma unroll
        for (int it = 0; it < 16; ++it) {
            uint32_t off = (uint32_t)(it * NTHREADS + tid) * 16u;
            asm volatile("cp.async.cg.shared.global [%0], [%1], 16;"
                         :: "r"(sb + off), "l"(wsrc + off) : "memory");
        }
        asm volatile("cp.async.commit_group;" ::: "memory");
    }

    // Per-thread constants for A conversion
    const int cr = tid >> 5;              // row within 64-row tile (for convert)
    const int cq = tid & 31;              // float4 column
    const uint32_t a_soff = (uint32_t)(cq >> 4) * A_CH_STRIDE +
                            SWZ((uint32_t)(cr * 128 + (cq & 15) * 8));

    // Warp tile: wid&1 -> m block (32 rows), wid>>1 -> n block (32 cols)
    const int m0 = (wid & 1) * 32;
    const int n0 = (wid >> 1) * 32;
    const int row_in = (lane & 7) + ((lane >> 3) & 1) * 8;
    const int kadd   = (lane >> 4) * 8;

    // Bias fragment (m==0 only)
    float2 bv[4];
#pragma unroll
    for (int nt = 0; nt < 4; ++nt) {
        int col = n0 + nt * 8 + (lane & 3) * 2;
        bv[nt].x = (m == 0) ? bias[col]     : 0.0f;
        bv[nt].y = (m == 0) ? bias[col + 1] : 0.0f;
    }

    for (int t = 0; t < NTILE; ++t) {
        const int b0 = (blockIdx.x * NTILE + t) * TILE_B;
        const float* aBase = in + ((size_t)b0 * NUM_M + m) * IN_F;

        // ---- Convert A tile (64x128 fp32 -> bf16 hi/lo, swizzled) ----
#pragma unroll
        for (int it = 0; it < 8; ++it) {
            int r = cr + it * 8;
            uint32_t soff = a_soff + (uint32_t)it * (8 * 128);
            float4 v = *reinterpret_cast<const float4*>(
                aBase + (size_t)r * (NUM_M * IN_F) + cq * 4);
            float hx = __bfloat162float(__float2bfloat16(v.x));
            float hy = __bfloat162float(__float2bfloat16(v.y));
            float hz = __bfloat162float(__float2bfloat16(v.z));
            float hw = __bfloat162float(__float2bfloat16(v.w));
            *reinterpret_cast<uint2*>(smem + AH_OFF + soff) =
                make_uint2(pack_bf16(v.x, v.y), pack_bf16(v.z, v.w));
            *reinterpret_cast<uint2*>(smem + AL_OFF + soff) =
                make_uint2(pack_bf16(v.x - hx, v.y - hy), pack_bf16(v.z - hz, v.w - hw));
        }
        asm volatile("cp.async.wait_group 0;" ::: "memory");
        __syncthreads();

        // ---- MMA: 8 k-steps, 3 split products ----
        float acc[2][4][4];
#pragma unroll
        for (int a = 0; a < 2; ++a)
#pragma unroll
            for (int b = 0; b < 4; ++b)
#pragma unroll
                for (int c = 0; c < 4; ++c) acc[a][b][c] = 0.0f;

#pragma unroll
        for (int ks = 0; ks < 8; ++ks) {
            const int kc    = ks * 16 + kadd;
            const int chunk = kc >> 6;
            const int kwi   = (kc & 63) * 2;

            uint32_t ah[2][4], al[2][4], wh[2][4], wl[2][4];
#pragma unroll
            for (int mt = 0; mt < 2; ++mt) {
                uint32_t addr = sb + AH_OFF + (uint32_t)chunk * A_CH_STRIDE +
                                SWZ((uint32_t)((m0 + mt * 16 + row_in) * 128 + kwi));
                LDSM4(ah[mt], addr);
                LDSM4(al[mt], addr + (AL_OFF - AH_OFF));
            }
#pragma unroll
            for (int g = 0; g < 2; ++g) {
                uint32_t addr = sb + (uint32_t)chunk * W_CH_STRIDE +
                                SWZ((uint32_t)((n0 + g * 16 + row_in) * 128 + kwi));
                LDSM4(wh[g], addr);
                LDSM4(wl[g], addr + WL_REL);
            }
#pragma unroll
            for (int mt = 0; mt < 2; ++mt) {
#pragma unroll
                for (int nt = 0; nt < 4; ++nt) {
                    const int g = nt >> 1, o = nt & 1;
                    MMA_BF16(acc[mt][nt], ah[mt], wh[g][o], wh[g][2 + o]);
                    MMA_BF16(acc[mt][nt], al[mt], wh[g][o], wh[g][2 + o]);
                    MMA_BF16(acc[mt][nt], ah[mt], wl[g][o], wl[g][2 + o]);
                }
            }
        }
        __syncthreads();   // A smem reused next tile

        // ---- Epilogue: direct STG.64 ----
#pragma unroll
        for (int mt = 0; mt < 2; ++mt) {
#pragma unroll
            for (int nt = 0; nt < 4; ++nt) {
#pragma unroll
                for (int h = 0; h < 2; ++h) {
                    int row = b0 + m0 + mt * 16 + (lane >> 2) + h * 8;
                    int col = n0 + nt * 8 + (lane & 3) * 2;
                    float2 v;
                    v.x = acc[mt][nt][2 * h]     + bv[nt].x;
                    v.y = acc[mt][nt][2 * h + 1] + bv[nt].y;
                    *reinterpret_cast<float2*>(
                        out + ((size_t)row * NUM_M + m) * OUT_F + col) = v;
                }
            }
        }
    }
}

extern "C" void kernel_launch(void* const* d_in, const int* in_sizes, int n_in,
                              void* d_out, int out_size) {
    const float* in   = (const float*)d_in[0];  // [16384, 25, 128]
    const float* w    = (const float*)d_in[1];  // [5, 128, 128]
    const float* bias = (const float*)d_in[2];  // [128]
    float* out        = (float*)d_out;          // [16384, 25, 128]

    so3_prep_w<<<5, NTHREADS>>>(w);

    cudaFuncSetAttribute(so3linear_hmma_kernel,
                         cudaFuncAttributeMaxDynamicSharedMemorySize, SMEM_BYTES);

    dim3 grid(BATCH / (TILE_B * NTILE), NUM_M);  // (64, 25) = 1600 CTAs
    so3linear_hmma_kernel<<<grid, NTHREADS, SMEM_BYTES>>>(in, bias, out);
}

// round 6
// speedup vs baseline: 4.2604x; 1.2292x over previous
#include <cuda_runtime.h>
#include <cuda_fp16.h>
#include <cstdint>

// SO3Linear via mma.sync fp16 (HMMA), 2-MMA scheme:
//   A = Ah + Al (fp16 hi/lo split, repr error ~2^-22)
//   W = Wh      (single RN fp16, error ~2^-12 -> rel_err ~2.4e-4 << 1e-3)
//   D = Ah*Wh + Al*Wh   (fp32 accumulators)
// W prepped once into SW128 smem-image fp16 layout; A converted per tile.
// 64KB smem/CTA -> 3 CTAs/SM for phase overlap.

#define BATCH    16384
#define NUM_M    25
#define IN_F     128
#define OUT_F    128
#define TILE_B   64
#define NTILE    4
#define NTHREADS 256

// W image per l: 32KB = 2 k-chunks (k 0..63 | 64..127) of 128 rows x 128B.
#define W_L_BYTES   32768
#define W_CH_STRIDE 16384
// smem: W at 0 (32KB), A hi at 32KB (2 chunks x 8KB), A lo at 48KB.
#define AH_OFF      32768
#define AL_OFF      49152
#define A_CH_STRIDE 8192
#define SMEM_BYTES  65536

#define SWZ(b) ((b) ^ (((b) >> 3) & 0x70))

__device__ __align__(128) uint8_t g_wprep[5 * W_L_BYTES];

__device__ __forceinline__ uint32_t smem_u32(const void* p) {
    uint32_t a;
    asm("{ .reg .u64 t; cvta.to.shared.u64 t, %1; cvt.u32.u64 %0, t; }" : "=r"(a) : "l"(p));
    return a;
}

#define LDSM4(r, addr) \
    asm volatile("ldmatrix.sync.aligned.m8n8.x4.shared.b16 {%0,%1,%2,%3}, [%4];" \
        : "=r"((r)[0]), "=r"((r)[1]), "=r"((r)[2]), "=r"((r)[3]) : "r"(addr))

#define MMA_F16(c, a, b0_, b1_) \
    asm volatile("mma.sync.aligned.m16n8k16.row.col.f32.f16.f16.f32 " \
        "{%0,%1,%2,%3},{%4,%5,%6,%7},{%8,%9},{%0,%1,%2,%3};" \
        : "+f"((c)[0]), "+f"((c)[1]), "+f"((c)[2]), "+f"((c)[3]) \
        : "r"((a)[0]), "r"((a)[1]), "r"((a)[2]), "r"((a)[3]), "r"(b0_), "r"(b1_))

__device__ __forceinline__ uint32_t pack_h2(float x, float y) {
    __half2 p = __floats2half2_rn(x, y);
    return *reinterpret_cast<uint32_t*>(&p);
}

// ---- Prep: W[l] -> centered fp16, SW128 smem-image layout in global ----
__global__ void so3_prep_w(const float* __restrict__ w) {
    const int l   = blockIdx.x;
    const int tid = threadIdx.x;
    const float bound = 0.088388347648318447f;  // 1/sqrt(128)
    uint8_t* dst = g_wprep + (size_t)l * W_L_BYTES;
    const float* src = w + (size_t)l * OUT_F * IN_F;
#pragma unroll
    for (int it = 0; it < 16; ++it) {
        int li = it * NTHREADS + tid;
        int r  = li >> 5;                 // out row 0..127
        int q  = li & 31;                 // float4 col, k0 = 4q
        uint32_t soff = (uint32_t)(q >> 4) * W_CH_STRIDE +
                        SWZ((uint32_t)(r * 128 + (q & 15) * 8));
        float4 v = *reinterpret_cast<const float4*>(src + (size_t)r * IN_F + q * 4);
        v.x -= bound; v.y -= bound; v.z -= bound; v.w -= bound;
        *reinterpret_cast<uint2*>(dst + soff) =
            make_uint2(pack_h2(v.x, v.y), pack_h2(v.z, v.w));
    }
}

// ---- Main kernel ----
__global__ __launch_bounds__(NTHREADS, 3)
void so3linear_hmma_kernel(const float* __restrict__ in,
                           const float* __restrict__ bias,
                           float* __restrict__ out) {
    extern __shared__ char smem[];
    const uint32_t sb = smem_u32(smem);

    const int tid  = threadIdx.x;
    const int wid  = tid >> 5;
    const int lane = tid & 31;
    const int m    = blockIdx.y;
    const int l    = (m >= 16) ? 4 : (m >= 9) ? 3 : (m >= 4) ? 2 : (m >= 1) ? 1 : 0;

    // ---- W: flat 32KB cp.async from prepped image ----
    {
        const uint8_t* wsrc = g_wprep + (size_t)l * W_L_BYTES;
#pragma unroll
        for (int it = 0; it < 8; ++it) {
            uint32_t off = (uint32_t)(it * NTHREADS + tid) * 16u;
            asm volatile("cp.async.cg.shared.global [%0], [%1], 16;"
                         :: "r"(sb + off), "l"(wsrc + off) : "memory");
        }
        asm volatile("cp.async.commit_group;" ::: "memory");
    }

    // Per-thread constants for A conversion
    const int cr = tid >> 5;              // row within 64-row tile
    const int cq = tid & 31;              // float4 column
    const uint32_t a_soff = (uint32_t)(cq >> 4) * A_CH_STRIDE +
                            SWZ((uint32_t)(cr * 128 + (cq & 15) * 8));

    // Warp tile: wid&1 -> m block (32 rows), wid>>1 -> n block (32 cols)
    const int m0 = (wid & 1) * 32;
    const int n0 = (wid >> 1) * 32;
    const int row_in = (lane & 7) + ((lane >> 3) & 1) * 8;
    const int kadd   = (lane >> 4) * 8;

    // Bias fragment (m==0 only)
    float2 bv[4];
#pragma unroll
    for (int nt = 0; nt < 4; ++nt) {
        int col = n0 + nt * 8 + (lane & 3) * 2;
        bv[nt].x = (m == 0) ? bias[col]     : 0.0f;
        bv[nt].y = (m == 0) ? bias[col + 1] : 0.0f;
    }

    for (int t = 0; t < NTILE; ++t) {
        const int b0 = (blockIdx.x * NTILE + t) * TILE_B;
        const float* aBase = in + ((size_t)b0 * NUM_M + m) * IN_F;

        // ---- Convert A tile (64x128 fp32 -> fp16 hi/lo, swizzled) ----
#pragma unroll
        for (int it = 0; it < 8; ++it) {
            int r = cr + it * 8;
            uint32_t soff = a_soff + (uint32_t)it * (8 * 128);
            float4 v = *reinterpret_cast<const float4*>(
                aBase + (size_t)r * (NUM_M * IN_F) + cq * 4);
            __half2 hxy = __floats2half2_rn(v.x, v.y);
            __half2 hzw = __floats2half2_rn(v.z, v.w);
            float2 fxy = __half22float2(hxy);
            float2 fzw = __half22float2(hzw);
            *reinterpret_cast<uint2*>(smem + AH_OFF + soff) =
                make_uint2(*reinterpret_cast<uint32_t*>(&hxy),
                           *reinterpret_cast<uint32_t*>(&hzw));
            *reinterpret_cast<uint2*>(smem + AL_OFF + soff) =
                make_uint2(pack_h2(v.x - fxy.x, v.y - fxy.y),
                           pack_h2(v.z - fzw.x, v.w - fzw.y));
        }
        asm volatile("cp.async.wait_group 0;" ::: "memory");
        __syncthreads();

        // ---- MMA: 8 k-steps, 2 split products (Ah*Wh + Al*Wh) ----
        float acc[2][4][4];
#pragma unroll
        for (int a = 0; a < 2; ++a)
#pragma unroll
            for (int b = 0; b < 4; ++b)
#pragma unroll
                for (int c = 0; c < 4; ++c) acc[a][b][c] = 0.0f;

#pragma unroll
        for (int ks = 0; ks < 8; ++ks) {
            const int kc    = ks * 16 + kadd;
            const int chunk = kc >> 6;
            const int kwi   = (kc & 63) * 2;

            uint32_t ah[2][4], al[2][4], wh[2][4];
#pragma unroll
            for (int mt = 0; mt < 2; ++mt) {
                uint32_t addr = sb + AH_OFF + (uint32_t)chunk * A_CH_STRIDE +
                                SWZ((uint32_t)((m0 + mt * 16 + row_in) * 128 + kwi));
                LDSM4(ah[mt], addr);
                LDSM4(al[mt], addr + (AL_OFF - AH_OFF));
            }
#pragma unroll
            for (int g = 0; g < 2; ++g) {
                uint32_t addr = sb + (uint32_t)chunk * W_CH_STRIDE +
                                SWZ((uint32_t)((n0 + g * 16 + row_in) * 128 + kwi));
                LDSM4(wh[g], addr);
            }
#pragma unroll
            for (int mt = 0; mt < 2; ++mt) {
#pragma unroll
                for (int nt = 0; nt < 4; ++nt) {
                    const int g = nt >> 1, o = nt & 1;
                    MMA_F16(acc[mt][nt], ah[mt], wh[g][o], wh[g][2 + o]);
                    MMA_F16(acc[mt][nt], al[mt], wh[g][o], wh[g][2 + o]);
                }
            }
        }
        __syncthreads();   // A smem reused next tile

        // ---- Epilogue: direct STG.64 ----
#pragma unroll
        for (int mt = 0; mt < 2; ++mt) {
#pragma unroll
            for (int nt = 0; nt < 4; ++nt) {
#pragma unroll
                for (int h = 0; h < 2; ++h) {
                    int row = b0 + m0 + mt * 16 + (lane >> 2) + h * 8;
                    int col = n0 + nt * 8 + (lane & 3) * 2;
                    float2 v;
                    v.x = acc[mt][nt][2 * h]     + bv[nt].x;
                    v.y = acc[mt][nt][2 * h + 1] + bv[nt].y;
                    *reinterpret_cast<float2*>(
                        out + ((size_t)row * NUM_M + m) * OUT_F + col) = v;
                }
            }
        }
    }
}

extern "C" void kernel_launch(void* const* d_in, const int* in_sizes, int n_in,
                              void* d_out, int out_size) {
    const float* in   = (const float*)d_in[0];  // [16384, 25, 128]
    const float* w    = (const float*)d_in[1];  // [5, 128, 128]
    const float* bias = (const float*)d_in[2];  // [128]
    float* out        = (float*)d_out;          // [16384, 25, 128]

    so3_prep_w<<<5, NTHREADS>>>(w);

    cudaFuncSetAttribute(so3linear_hmma_kernel,
                         cudaFuncAttributeMaxDynamicSharedMemorySize, SMEM_BYTES);

    dim3 grid(BATCH / (TILE_B * NTILE), NUM_M);  // (64, 25) = 1600 CTAs
    so3linear_hmma_kernel<<<grid, NTHREADS, SMEM_BYTES>>>(in, bias, out);
}

// round 7
// speedup vs baseline: 4.7150x; 1.1067x over previous
#include <cuda_runtime.h>
#include <cuda_fp16.h>
#include <cstdint>

// SO3Linear via mma.sync fp16 (HMMA), single-MMA scheme:
//   A -> fp16 RN, W -> centered fp16 RN, D = A16 * W16^T in fp32 accum.
//   Calibrated error: W-only quant gave 2.16e-4; A adds same magnitude
//   independently -> ~3.1e-4 total, 3x inside the 1e-3 budget.
// W prepped once into SW128 smem-image fp16 layout (5 matrices, L2-resident).
// 48KB smem/CTA + <=64 regs -> 4 CTAs/SM for phase overlap.

#define BATCH    16384
#define NUM_M    25
#define IN_F     128
#define OUT_F    128
#define TILE_B   64
#define NTILE    4
#define NTHREADS 256

// W image per l: 32KB = 2 k-chunks (k 0..63 | 64..127) of 128 rows x 128B.
#define W_L_BYTES   32768
#define W_CH_STRIDE 16384
// smem: W at 0 (32KB), A at 32KB (2 chunks x 8KB).
#define A_OFF       32768
#define A_CH_STRIDE 8192
#define SMEM_BYTES  49152

#define SWZ(b) ((b) ^ (((b) >> 3) & 0x70))

__device__ __align__(128) uint8_t g_wprep[5 * W_L_BYTES];

__device__ __forceinline__ uint32_t smem_u32(const void* p) {
    uint32_t a;
    asm("{ .reg .u64 t; cvta.to.shared.u64 t, %1; cvt.u32.u64 %0, t; }" : "=r"(a) : "l"(p));
    return a;
}

#define LDSM4(r, addr) \
    asm volatile("ldmatrix.sync.aligned.m8n8.x4.shared.b16 {%0,%1,%2,%3}, [%4];" \
        : "=r"((r)[0]), "=r"((r)[1]), "=r"((r)[2]), "=r"((r)[3]) : "r"(addr))

#define MMA_F16(c, a, b0_, b1_) \
    asm volatile("mma.sync.aligned.m16n8k16.row.col.f32.f16.f16.f32 " \
        "{%0,%1,%2,%3},{%4,%5,%6,%7},{%8,%9},{%0,%1,%2,%3};" \
        : "+f"((c)[0]), "+f"((c)[1]), "+f"((c)[2]), "+f"((c)[3]) \
        : "r"((a)[0]), "r"((a)[1]), "r"((a)[2]), "r"((a)[3]), "r"(b0_), "r"(b1_))

__device__ __forceinline__ uint32_t pack_h2(float x, float y) {
    __half2 p = __floats2half2_rn(x, y);
    return *reinterpret_cast<uint32_t*>(&p);
}

// ---- Prep: W[l] -> centered fp16, SW128 smem-image layout in global ----
__global__ void so3_prep_w(const float* __restrict__ w) {
    const int l   = blockIdx.x;
    const int tid = threadIdx.x;
    const float bound = 0.088388347648318447f;  // 1/sqrt(128)
    uint8_t* dst = g_wprep + (size_t)l * W_L_BYTES;
    const float* src = w + (size_t)l * OUT_F * IN_F;
#pragma unroll
    for (int it = 0; it < 16; ++it) {
        int li = it * NTHREADS + tid;
        int r  = li >> 5;                 // out row 0..127
        int q  = li & 31;                 // float4 col, k0 = 4q
        uint32_t soff = (uint32_t)(q >> 4) * W_CH_STRIDE +
                        SWZ((uint32_t)(r * 128 + (q & 15) * 8));
        float4 v = *reinterpret_cast<const float4*>(src + (size_t)r * IN_F + q * 4);
        v.x -= bound; v.y -= bound; v.z -= bound; v.w -= bound;
        *reinterpret_cast<uint2*>(dst + soff) =
            make_uint2(pack_h2(v.x, v.y), pack_h2(v.z, v.w));
    }
}

// ---- Main kernel ----
__global__ __launch_bounds__(NTHREADS, 4)
void so3linear_hmma_kernel(const float* __restrict__ in,
                           const float* __restrict__ bias,
                           float* __restrict__ out) {
    extern __shared__ char smem[];
    const uint32_t sb = smem_u32(smem);

    const int tid  = threadIdx.x;
    const int wid  = tid >> 5;
    const int lane = tid & 31;
    const int m    = blockIdx.y;
    const int l    = (m >= 16) ? 4 : (m >= 9) ? 3 : (m >= 4) ? 2 : (m >= 1) ? 1 : 0;

    // ---- W: flat 32KB cp.async from prepped image ----
    {
        const uint8_t* wsrc = g_wprep + (size_t)l * W_L_BYTES;
#pragma unroll
        for (int it = 0; it < 8; ++it) {
            uint32_t off = (uint32_t)(it * NTHREADS + tid) * 16u;
            asm volatile("cp.async.cg.shared.global [%0], [%1], 16;"
                         :: "r"(sb + off), "l"(wsrc + off) : "memory");
        }
        asm volatile("cp.async.commit_group;" ::: "memory");
    }

    // Per-thread constants for A conversion
    const int cr = tid >> 5;              // row within 64-row tile
    const int cq = tid & 31;              // float4 column
    const uint32_t a_soff = (uint32_t)(cq >> 4) * A_CH_STRIDE +
                            SWZ((uint32_t)(cr * 128 + (cq & 15) * 8));

    // Warp tile: wid&1 -> m block (32 rows), wid>>1 -> n block (32 cols)
    const int m0 = (wid & 1) * 32;
    const int n0 = (wid >> 1) * 32;
    const int row_in = (lane & 7) + ((lane >> 3) & 1) * 8;
    const int kadd   = (lane >> 4) * 8;

    // Bias fragment (m==0 only)
    float2 bv[4];
#pragma unroll
    for (int nt = 0; nt < 4; ++nt) {
        int col = n0 + nt * 8 + (lane & 3) * 2;
        bv[nt].x = (m == 0) ? bias[col]     : 0.0f;
        bv[nt].y = (m == 0) ? bias[col + 1] : 0.0f;
    }

    for (int t = 0; t < NTILE; ++t) {
        const int b0 = (blockIdx.x * NTILE + t) * TILE_B;
        const float* aBase = in + ((size_t)b0 * NUM_M + m) * IN_F;

        // ---- Convert A tile (64x128 fp32 -> fp16 RN, swizzled) ----
#pragma unroll
        for (int it = 0; it < 8; ++it) {
            int r = cr + it * 8;
            uint32_t soff = a_soff + (uint32_t)it * (8 * 128);
            float4 v = *reinterpret_cast<const float4*>(
                aBase + (size_t)r * (NUM_M * IN_F) + cq * 4);
            *reinterpret_cast<uint2*>(smem + A_OFF + soff) =
                make_uint2(pack_h2(v.x, v.y), pack_h2(v.z, v.w));
        }
        asm volatile("cp.async.wait_group 0;" ::: "memory");
        __syncthreads();

        // ---- MMA: 8 k-steps, single product ----
        float acc[2][4][4];
#pragma unroll
        for (int a = 0; a < 2; ++a)
#pragma unroll
            for (int b = 0; b < 4; ++b)
#pragma unroll
                for (int c = 0; c < 4; ++c) acc[a][b][c] = 0.0f;

#pragma unroll
        for (int ks = 0; ks < 8; ++ks) {
            const int kc    = ks * 16 + kadd;
            const int chunk = kc >> 6;
            const int kwi   = (kc & 63) * 2;

            uint32_t ah[2][4], wh[2][4];
#pragma unroll
            for (int mt = 0; mt < 2; ++mt) {
                uint32_t addr = sb + A_OFF + (uint32_t)chunk * A_CH_STRIDE +
                                SWZ((uint32_t)((m0 + mt * 16 + row_in) * 128 + kwi));
                LDSM4(ah[mt], addr);
            }
#pragma unroll
            for (int g = 0; g < 2; ++g) {
                uint32_t addr = sb + (uint32_t)chunk * W_CH_STRIDE +
                                SWZ((uint32_t)((n0 + g * 16 + row_in) * 128 + kwi));
                LDSM4(wh[g], addr);
            }
#pragma unroll
            for (int mt = 0; mt < 2; ++mt) {
#pragma unroll
                for (int nt = 0; nt < 4; ++nt) {
                    const int g = nt >> 1, o = nt & 1;
                    MMA_F16(acc[mt][nt], ah[mt], wh[g][o], wh[g][2 + o]);
                }
            }
        }
        __syncthreads();   // A smem reused next tile

        // ---- Epilogue: direct STG.64 ----
#pragma unroll
        for (int mt = 0; mt < 2; ++mt) {
#pragma unroll
            for (int nt = 0; nt < 4; ++nt) {
#pragma unroll
                for (int h = 0; h < 2; ++h) {
                    int row = b0 + m0 + mt * 16 + (lane >> 2) + h * 8;
                    int col = n0 + nt * 8 + (lane & 3) * 2;
                    float2 v;
                    v.x = acc[mt][nt][2 * h]     + bv[nt].x;
                    v.y = acc[mt][nt][2 * h + 1] + bv[nt].y;
                    *reinterpret_cast<float2*>(
                        out + ((size_t)row * NUM_M + m) * OUT_F + col) = v;
                }
            }
        }
    }
}

extern "C" void kernel_launch(void* const* d_in, const int* in_sizes, int n_in,
                              void* d_out, int out_size) {
    const float* in   = (const float*)d_in[0];  // [16384, 25, 128]
    const float* w    = (const float*)d_in[1];  // [5, 128, 128]
    const float* bias = (const float*)d_in[2];  // [128]
    float* out        = (float*)d_out;          // [16384, 25, 128]

    so3_prep_w<<<5, NTHREADS>>>(w);

    cudaFuncSetAttribute(so3linear_hmma_kernel,
                         cudaFuncAttributeMaxDynamicSharedMemorySize, SMEM_BYTES);

    dim3 grid(BATCH / (TILE_B * NTILE), NUM_M);  // (64, 25) = 1600 CTAs
    so3linear_hmma_kernel<<<grid, NTHREADS, SMEM_BYTES>>>(in, bias, out);
}